// round 3
// baseline (speedup 1.0000x reference)
#include <cuda_runtime.h>

// LayerwiseLowRankUplift: out = z + U_l (V_l^T z), per-sample layer l.
// B=2048, H=2048, R=64, L=32. Strategy: bucket samples by layer, then two
// grouped GEMM-ish kernels so u/v tiles are reused across samples via smem.

#define HDIM 2048
#define RDIM 64
#define LNUM 32
#define BMAX 2048

#define TBA 16   // samples per proj tile
#define TBB 32   // samples per delta tile
#define HC  64   // H chunk

// ---- scratch (device globals; no allocation allowed) ----
__device__ int   g_counts[LNUM];
__device__ int   g_index[LNUM][BMAX];
__device__ float g_proj[BMAX][RDIM];

// ============================================================
// Kernel 0: bucket sample indices by layer. One block per layer.
// ============================================================
__global__ __launch_bounds__(256) void bucket_kernel(const int* __restrict__ layer_ids, int B) {
    __shared__ int cur;
    const int l = blockIdx.x;
    if (threadIdx.x == 0) cur = 0;
    __syncthreads();
    for (int i = threadIdx.x; i < B; i += 256) {
        if (layer_ids[i] == l) {
            int p = atomicAdd(&cur, 1);
            g_index[l][p] = i;
        }
    }
    __syncthreads();
    if (threadIdx.x == 0) g_counts[l] = cur;
}

// ============================================================
// Kernel A: proj[b][r] = sum_h v[l][h][r] * z[b][h]
// grid = (LNUM, ceil(B/TBA)), 256 threads.
// Thread tile: 1 sample x 4 r. Z tile stored transposed [h][b] (pad 17).
// ============================================================
__global__ __launch_bounds__(256) void proj_kernel(const float* __restrict__ z,
                                                   const float* __restrict__ v) {
    const int l = blockIdx.x;
    const int n = g_counts[l];
    const int s0 = blockIdx.y * TBA;
    if (s0 >= n) return;

    __shared__ float Vs[HC * RDIM];        // [h][r], natural layout
    __shared__ float Zs[HC * 17];          // [h][b], padded stride 17
    __shared__ int   s_idx[TBA];

    const int tid = threadIdx.x;
    if (tid < TBA) {
        int j = s0 + tid;
        s_idx[tid] = g_index[l][j < n ? j : 0];   // clamp tail to a valid row
    }
    __syncthreads();

    const int bx = tid & 15;        // sample within tile
    const int ry = tid >> 4;        // r quad (0..15)

    float acc0 = 0.f, acc1 = 0.f, acc2 = 0.f, acc3 = 0.f;
    const float* vbase = v + (size_t)l * HDIM * RDIM;

    const int hh = tid & 63;        // Z-loader h
    const int bb0 = tid >> 6;       // Z-loader b base (0..3)

    for (int hc = 0; hc < HDIM; hc += HC) {
        // load V chunk: 64x64 floats, fully coalesced
        {
            const float4* v4 = (const float4*)(vbase + (size_t)hc * RDIM);
            float4* Vs4 = (float4*)Vs;
            #pragma unroll
            for (int k = 0; k < 4; k++) Vs4[tid + k * 256] = v4[tid + k * 256];
        }
        // load Z chunk transposed: Zs[h][b]
        {
            #pragma unroll
            for (int k = 0; k < 4; k++) {
                int b = bb0 + k * 4;
                Zs[hh * 17 + b] = z[(size_t)s_idx[b] * HDIM + hc + hh];
            }
        }
        __syncthreads();

        #pragma unroll 16
        for (int h = 0; h < HC; h++) {
            float  zz = Zs[h * 17 + bx];
            float4 vv = *(const float4*)(Vs + h * RDIM + 4 * ry);
            acc0 += zz * vv.x;
            acc1 += zz * vv.y;
            acc2 += zz * vv.z;
            acc3 += zz * vv.w;
        }
        __syncthreads();
    }

    if (s0 + bx < n) {
        float4 o = make_float4(acc0, acc1, acc2, acc3);
        *(float4*)(&g_proj[s_idx[bx]][4 * ry]) = o;
    }
}

// ============================================================
// Kernel B: out[b][h] = z[b][h] + sum_r u[l][h][r] * proj[b][r]
// grid = (LNUM, ceil(B/TBB), HDIM/256), 256 threads.
// Thread tile: 2 samples x 4 h (contiguous quad).
// U chunk stored transposed [r][h] (stride 68) for conflict-free LDS.128.
// ============================================================
__global__ __launch_bounds__(256) void delta_kernel(const float* __restrict__ z,
                                                    const float* __restrict__ u,
                                                    float* __restrict__ out) {
    const int l = blockIdx.x;
    const int n = g_counts[l];
    const int s0 = blockIdx.y * TBB;
    if (s0 >= n) return;
    const int hbase = blockIdx.z * 256;

    __shared__ float UsT[RDIM * 68];       // [r][h], padded stride 68
    __shared__ float Ps[TBB * RDIM];       // [b][r]
    __shared__ int   s_idx[TBB];

    const int tid = threadIdx.x;
    if (tid < TBB) {
        int j = s0 + tid;
        s_idx[tid] = g_index[l][j < n ? j : 0];
    }
    __syncthreads();

    // load proj tile: 32x64 floats (coalesced per-sample rows)
    {
        #pragma unroll
        for (int k = 0; k < 2; k++) {
            int fid = tid + k * 256;
            int b  = fid >> 4;
            int r4 = fid & 15;
            ((float4*)(Ps + b * RDIM))[r4] = ((const float4*)(g_proj[s_idx[b]]))[r4];
        }
    }

    const int hx  = tid & 15;       // h quad -> h0 = 4*hx
    const int byy = tid >> 4;       // 0..15 -> b0 = 2*byy
    const int b0  = byy * 2;
    const float* ubase = u + (size_t)l * HDIM * RDIM;

    const int rl = tid & 63;        // U-loader r
    const int hl0 = tid >> 6;       // U-loader h base (0..3)

    for (int hc = 0; hc < 256; hc += HC) {
        __syncthreads();   // protect UsT reuse + first Ps consumption ordering
        // load U chunk transposed: UsT[r][h]
        {
            #pragma unroll
            for (int k = 0; k < 16; k++) {
                int h = hl0 + 4 * k;
                UsT[rl * 68 + h] = ubase[(size_t)(hbase + hc + h) * RDIM + rl];
            }
        }
        __syncthreads();

        float a00 = 0.f, a01 = 0.f, a02 = 0.f, a03 = 0.f;
        float a10 = 0.f, a11 = 0.f, a12 = 0.f, a13 = 0.f;
        #pragma unroll 8
        for (int r = 0; r < RDIM; r++) {
            float4 uu = *(const float4*)(UsT + r * 68 + 4 * hx);
            float  pa = Ps[b0 * RDIM + r];
            float  pb = Ps[(b0 + 1) * RDIM + r];
            a00 += pa * uu.x;  a01 += pa * uu.y;  a02 += pa * uu.z;  a03 += pa * uu.w;
            a10 += pb * uu.x;  a11 += pb * uu.y;  a12 += pb * uu.z;  a13 += pb * uu.w;
        }

        const int hg = hbase + hc + 4 * hx;
        if (s0 + b0 < n) {
            size_t off = (size_t)s_idx[b0] * HDIM + hg;
            float4 zz = *(const float4*)(z + off);
            float4 o = make_float4(zz.x + a00, zz.y + a01, zz.z + a02, zz.w + a03);
            *(float4*)(out + off) = o;
        }
        if (s0 + b0 + 1 < n) {
            size_t off = (size_t)s_idx[b0 + 1] * HDIM + hg;
            float4 zz = *(const float4*)(z + off);
            float4 o = make_float4(zz.x + a10, zz.y + a11, zz.z + a12, zz.w + a13);
            *(float4*)(out + off) = o;
        }
    }
}

// ============================================================
extern "C" void kernel_launch(void* const* d_in, const int* in_sizes, int n_in,
                              void* d_out, int out_size) {
    const float* z   = (const float*)d_in[0];
    const int*   lid = (const int*)d_in[1];
    const float* u   = (const float*)d_in[2];
    const float* v   = (const float*)d_in[3];
    float* out = (float*)d_out;
    const int B = in_sizes[1];   // layer_ids element count == batch

    bucket_kernel<<<LNUM, 256>>>(lid, B);
    proj_kernel<<<dim3(LNUM, (B + TBA - 1) / TBA), 256>>>(z, v);
    delta_kernel<<<dim3(LNUM, (B + TBB - 1) / TBB, HDIM / 256), 256>>>(z, u, out);
}

// round 4
// speedup vs baseline: 1.0533x; 1.0533x over previous
#include <cuda_runtime.h>

// LayerwiseLowRankUplift: out = z + U_l (V_l^T z), per-sample layer l.
// B=2048, H=2048, R=64, L=32.
// R3: f32x2 packed FMA + 4x4 register tiles + K-split for occupancy.

#define HDIM 2048
#define RDIM 64
#define LNUM 32
#define BMAX 2048

#define KSPLIT 8
#define KRANGE (HDIM / KSPLIT)   // 256
#define KC     32                // inner k chunk
#define MTILE  64                // samples per tile
#define MTA    4                 // max M tiles (covers n <= 256; binomial mean 64)
#define HTILE  64
#define RC     32

#define ZP_STRIDE 68             // [k][b] rows, 16B-aligned pad
#define VD_STRIDE 136            // [k][2r] duplicated rows, 16B-aligned pad

// ---- scratch (device globals; no allocation allowed) ----
__device__ int   g_counts[LNUM];
__device__ int   g_index[LNUM][BMAX];
__device__ float g_projp[KSPLIT][BMAX][RDIM];   // K-split partials (4 MB)
__device__ float g_proj[BMAX][RDIM];

// packed fp32 pair FMA: acc = a*b + acc, lanewise on (lo,hi)
#define FMA2(acc, a, b) \
    asm("fma.rn.f32x2 %0, %1, %2, %0;" : "+l"(acc) : "l"(a), "l"(b))

__device__ __forceinline__ float f2lo(unsigned long long a) {
    return __uint_as_float((unsigned)a);
}
__device__ __forceinline__ float f2hi(unsigned long long a) {
    return __uint_as_float((unsigned)(a >> 32));
}

// ============================================================
// Kernel 0: bucket sample indices by layer. One block per layer.
// (int-atomic slot order is arbitrary but per-sample results are
//  slot-independent -> output bitwise deterministic)
// ============================================================
__global__ __launch_bounds__(256) void bucket_kernel(const int* __restrict__ ids, int B) {
    __shared__ int cur;
    const int l = blockIdx.x;
    if (threadIdx.x == 0) cur = 0;
    __syncthreads();
    const int4* ids4 = (const int4*)ids;
    for (int i = threadIdx.x; i < B / 4; i += 256) {
        int4 w = ids4[i];
        if (w.x == l) g_index[l][atomicAdd(&cur, 1)] = 4 * i;
        if (w.y == l) g_index[l][atomicAdd(&cur, 1)] = 4 * i + 1;
        if (w.z == l) g_index[l][atomicAdd(&cur, 1)] = 4 * i + 2;
        if (w.w == l) g_index[l][atomicAdd(&cur, 1)] = 4 * i + 3;
    }
    __syncthreads();
    if (threadIdx.x == 0) g_counts[l] = cur;
}

// ============================================================
// Kernel A: proj partials.  projp[ks][b][r] = sum_{k in split} v[l][k][r]*z[b][k]
// grid = (LNUM, MTA, KSPLIT), 256 threads.
// Block tile: 64 samples x 64 r.  Thread: 4 samples (2 f32x2 pairs) x 4 r.
// Zp: [k][b] transposed (pairs = consecutive samples).  Vd: [k][r] duplicated.
// ============================================================
__global__ __launch_bounds__(256) void proj_kernel(const float* __restrict__ z,
                                                   const float* __restrict__ v) {
    const int l = blockIdx.x;
    const int n = g_counts[l];
    const int s0 = blockIdx.y * MTILE;
    if (s0 >= n) return;
    const int ks = blockIdx.z;
    const int k0 = ks * KRANGE;

    __shared__ float Zp[KC * ZP_STRIDE];
    __shared__ float Vd[KC * VD_STRIDE];
    __shared__ int   sidx[MTILE];

    const int tid = threadIdx.x;
    if (tid < MTILE) {
        int j = s0 + tid;
        sidx[tid] = g_index[l][j < n ? j : n - 1];
    }
    __syncthreads();

    const int bx = tid & 15;   // sample quad -> samples 4bx..4bx+3
    const int ry = tid >> 4;   // r quad     -> r 4ry..4ry+3

    unsigned long long acc[2][4];
#pragma unroll
    for (int p = 0; p < 2; p++)
#pragma unroll
        for (int r = 0; r < 4; r++) acc[p][r] = 0ull;

    const float* vb = v + ((size_t)l * HDIM + k0) * RDIM;
    const int zlb = tid >> 5;   // z-loader sample base
    const int zlk = tid & 31;   // z-loader k (coalesced)

    for (int kc = 0; kc < KRANGE; kc += KC) {
        // Z chunk: 64 samples x 32 k, coalesced 128B per warp, transposed store
#pragma unroll
        for (int i = 0; i < 8; i++) {
            int b = zlb + 8 * i;
            Zp[zlk * ZP_STRIDE + b] = z[(size_t)sidx[b] * HDIM + k0 + kc + zlk];
        }
        // V chunk: 32 k x 64 r, each value stored duplicated (f32x2-ready)
#pragma unroll
        for (int i = 0; i < 2; i++) {
            int idx = tid + 256 * i;
            int k  = idx >> 4;
            int r4 = (idx & 15) * 4;
            float4 vv = *(const float4*)(vb + (size_t)(kc + k) * RDIM + r4);
            float2* d = (float2*)(Vd + k * VD_STRIDE + 2 * r4);
            d[0] = make_float2(vv.x, vv.x);
            d[1] = make_float2(vv.y, vv.y);
            d[2] = make_float2(vv.z, vv.z);
            d[3] = make_float2(vv.w, vv.w);
        }
        __syncthreads();

#pragma unroll
        for (int k = 0; k < KC; k++) {
            ulonglong2 zz  = *(const ulonglong2*)(Zp + k * ZP_STRIDE + 4 * bx);
            ulonglong2 va  = *(const ulonglong2*)(Vd + k * VD_STRIDE + 8 * ry);
            ulonglong2 vb2 = *(const ulonglong2*)(Vd + k * VD_STRIDE + 8 * ry + 4);
            FMA2(acc[0][0], zz.x, va.x);
            FMA2(acc[0][1], zz.x, va.y);
            FMA2(acc[0][2], zz.x, vb2.x);
            FMA2(acc[0][3], zz.x, vb2.y);
            FMA2(acc[1][0], zz.y, va.x);
            FMA2(acc[1][1], zz.y, va.y);
            FMA2(acc[1][2], zz.y, vb2.x);
            FMA2(acc[1][3], zz.y, vb2.y);
        }
        __syncthreads();
    }

    // store partials (masked tail)
#pragma unroll
    for (int p = 0; p < 2; p++) {
#pragma unroll
        for (int j = 0; j < 2; j++) {
            int s = 4 * bx + 2 * p + j;
            if (s0 + s < n) {
                float4 o;
                o.x = j ? f2hi(acc[p][0]) : f2lo(acc[p][0]);
                o.y = j ? f2hi(acc[p][1]) : f2lo(acc[p][1]);
                o.z = j ? f2hi(acc[p][2]) : f2lo(acc[p][2]);
                o.w = j ? f2hi(acc[p][3]) : f2lo(acc[p][3]);
                *(float4*)&g_projp[ks][sidx[s]][4 * ry] = o;
            }
        }
    }
}

// ============================================================
// Kernel A2: reduce K-split partials (fixed order -> deterministic)
// grid = BMAX*RDIM/4/256 = 128 blocks
// ============================================================
__global__ __launch_bounds__(256) void reduce_kernel() {
    const int idx = blockIdx.x * 256 + threadIdx.x;   // float4 index
    const float4* p = (const float4*)g_projp;
    const int stride = BMAX * RDIM / 4;
    float4 a = p[idx];
#pragma unroll
    for (int s = 1; s < KSPLIT; s++) {
        float4 b = p[s * stride + idx];
        a.x += b.x; a.y += b.y; a.z += b.z; a.w += b.w;
    }
    ((float4*)g_proj)[idx] = a;
}

// ============================================================
// Kernel B: out[b][h] = z[b][h] + sum_r u[l][h][r] * proj[b][r]
// grid = (LNUM, MTA, HDIM/HTILE), 256 threads.
// Block tile: 64 samples x 64 h.  Thread: 4 samples (2 pairs) x 4 h.
// Ps: [r][b] transposed.  Ud: [r][h] duplicated (chunks of RC).
// ============================================================
__global__ __launch_bounds__(256) void delta_kernel(const float* __restrict__ z,
                                                    const float* __restrict__ u,
                                                    float* __restrict__ out) {
    const int l = blockIdx.x;
    const int n = g_counts[l];
    const int s0 = blockIdx.y * MTILE;
    if (s0 >= n) return;
    const int hb = blockIdx.z * HTILE;

    __shared__ float Ps[RDIM * ZP_STRIDE];   // [r][b]
    __shared__ float Ud[RC * VD_STRIDE];     // [r][2h] duplicated
    __shared__ int   sidx[MTILE];

    const int tid = threadIdx.x;
    if (tid < MTILE) {
        int j = s0 + tid;
        sidx[tid] = g_index[l][j < n ? j : n - 1];
    }
    __syncthreads();

    // load + transpose proj tile: thread owns 1/4 of one sample's row
    {
        int b = tid >> 2, q = tid & 3;
        const float* pr = g_proj[sidx[b]];
#pragma unroll
        for (int j = 0; j < 4; j++) {
            int r0 = q * 16 + 4 * j;
            float4 pv = *(const float4*)(pr + r0);
            Ps[(r0 + 0) * ZP_STRIDE + b] = pv.x;
            Ps[(r0 + 1) * ZP_STRIDE + b] = pv.y;
            Ps[(r0 + 2) * ZP_STRIDE + b] = pv.z;
            Ps[(r0 + 3) * ZP_STRIDE + b] = pv.w;
        }
    }

    const int bx = tid & 15;   // sample quad
    const int hy = tid >> 4;   // h quad
    unsigned long long acc[2][4];
#pragma unroll
    for (int p = 0; p < 2; p++)
#pragma unroll
        for (int r = 0; r < 4; r++) acc[p][r] = 0ull;

    const float* ub = u + ((size_t)l * HDIM + hb) * RDIM;

    for (int rc = 0; rc < RDIM; rc += RC) {
        __syncthreads();   // Ps visibility (1st iter) + Ud reuse
        // U chunk: 64 h x 32 r, transposed + duplicated.
        // lanes vary h (2-way-ish store conflicts), rg fixed per warp.
#pragma unroll
        for (int i = 0; i < 2; i++) {
            int idx = tid + 256 * i;
            int rg = idx >> 6;          // 0..7 -> r4 = 4*rg
            int h  = idx & 63;
            int r4 = rg * 4;
            float4 uu = *(const float4*)(ub + (size_t)h * RDIM + rc + r4);
            Ud[(r4 + 0) * VD_STRIDE + 2 * h] = uu.x;
            Ud[(r4 + 0) * VD_STRIDE + 2 * h + 1] = uu.x;
            Ud[(r4 + 1) * VD_STRIDE + 2 * h] = uu.y;
            Ud[(r4 + 1) * VD_STRIDE + 2 * h + 1] = uu.y;
            Ud[(r4 + 2) * VD_STRIDE + 2 * h] = uu.z;
            Ud[(r4 + 2) * VD_STRIDE + 2 * h + 1] = uu.z;
            Ud[(r4 + 3) * VD_STRIDE + 2 * h] = uu.w;
            Ud[(r4 + 3) * VD_STRIDE + 2 * h + 1] = uu.w;
        }
        __syncthreads();

#pragma unroll
        for (int r = 0; r < RC; r++) {
            ulonglong2 pp  = *(const ulonglong2*)(Ps + (rc + r) * ZP_STRIDE + 4 * bx);
            ulonglong2 ua  = *(const ulonglong2*)(Ud + r * VD_STRIDE + 8 * hy);
            ulonglong2 ub2 = *(const ulonglong2*)(Ud + r * VD_STRIDE + 8 * hy + 4);
            FMA2(acc[0][0], pp.x, ua.x);
            FMA2(acc[0][1], pp.x, ua.y);
            FMA2(acc[0][2], pp.x, ub2.x);
            FMA2(acc[0][3], pp.x, ub2.y);
            FMA2(acc[1][0], pp.y, ua.x);
            FMA2(acc[1][1], pp.y, ua.y);
            FMA2(acc[1][2], pp.y, ub2.x);
            FMA2(acc[1][3], pp.y, ub2.y);
        }
    }

    // epilogue: delta + z -> out (masked tail)
#pragma unroll
    for (int p = 0; p < 2; p++) {
#pragma unroll
        for (int j = 0; j < 2; j++) {
            int s = 4 * bx + 2 * p + j;
            if (s0 + s < n) {
                size_t off = (size_t)sidx[s] * HDIM + hb + 4 * hy;
                float4 zz = *(const float4*)(z + off);
                float4 o;
                o.x = zz.x + (j ? f2hi(acc[p][0]) : f2lo(acc[p][0]));
                o.y = zz.y + (j ? f2hi(acc[p][1]) : f2lo(acc[p][1]));
                o.z = zz.z + (j ? f2hi(acc[p][2]) : f2lo(acc[p][2]));
                o.w = zz.w + (j ? f2hi(acc[p][3]) : f2lo(acc[p][3]));
                *(float4*)(out + off) = o;
            }
        }
    }
}

// ============================================================
extern "C" void kernel_launch(void* const* d_in, const int* in_sizes, int n_in,
                              void* d_out, int out_size) {
    const float* z   = (const float*)d_in[0];
    const int*   lid = (const int*)d_in[1];
    const float* u   = (const float*)d_in[2];
    const float* v   = (const float*)d_in[3];
    float* out = (float*)d_out;
    const int B = in_sizes[1];

    bucket_kernel<<<LNUM, 256>>>(lid, B);
    proj_kernel<<<dim3(LNUM, MTA, KSPLIT), 256>>>(z, v);
    reduce_kernel<<<(BMAX * RDIM / 4) / 256, 256>>>();
    delta_kernel<<<dim3(LNUM, MTA, HDIM / HTILE), 256>>>(z, u, out);
}

// round 7
// speedup vs baseline: 1.4456x; 1.3725x over previous
#include <cuda_runtime.h>

// LayerwiseLowRankUplift: out = z + U_l (V_l^T z), per-sample layer l.
// B=2048, H=2048, R=64, L=32.
// R4: 8x8 register tiles, f32x2 paired over output dim, register-packed
// broadcasts (no smem duplication) -> arithmetic intensity 1.0 vs crossbar.

#define HDIM 2048
#define RDIM 64
#define LNUM 32
#define BMAX 2048

#define MTILE 64      // samples per block tile
#define MTA   4       // max sample tiles per layer

// proj
#define KSPLIT 32
#define KRANGE (HDIM / KSPLIT)   // 64
#define KC     16                // k chunk in smem
#define ZPS    68                // Zp row stride (floats)

// delta
#define HTILE 128
#define RC    32
#define PSS   68                 // Ps row stride
#define UTS   136                // Ut row stride

// ---- scratch (device globals; no allocation allowed) ----
__device__ int   g_counts[LNUM];
__device__ int   g_index[LNUM][BMAX];
__device__ float g_projp[KSPLIT][BMAX][RDIM];   // 16 MB partials
__device__ float g_proj[BMAX][RDIM];

// packed fp32 pair FMA: acc = a*b + acc, lanewise on (lo,hi)
#define FMA2(acc, a, b) \
    asm("fma.rn.f32x2 %0, %1, %2, %0;" : "+l"(acc) : "l"(a), "l"(b))

__device__ __forceinline__ unsigned long long dup2(float x) {
    unsigned long long r;
    unsigned xi = __float_as_uint(x);
    asm("mov.b64 %0, {%1, %1};" : "=l"(r) : "r"(xi));
    return r;
}
__device__ __forceinline__ float f2lo(unsigned long long a) {
    return __uint_as_float((unsigned)a);
}
__device__ __forceinline__ float f2hi(unsigned long long a) {
    return __uint_as_float((unsigned)(a >> 32));
}

// ============================================================
// Kernel 0: bucket sample indices by layer. One block per layer.
// ============================================================
__global__ __launch_bounds__(256) void bucket_kernel(const int* __restrict__ ids, int B) {
    __shared__ int cur;
    const int l = blockIdx.x;
    if (threadIdx.x == 0) cur = 0;
    __syncthreads();
    const int4* ids4 = (const int4*)ids;
    for (int i = threadIdx.x; i < B / 4; i += 256) {
        int4 w = ids4[i];
        if (w.x == l) g_index[l][atomicAdd(&cur, 1)] = 4 * i;
        if (w.y == l) g_index[l][atomicAdd(&cur, 1)] = 4 * i + 1;
        if (w.z == l) g_index[l][atomicAdd(&cur, 1)] = 4 * i + 2;
        if (w.w == l) g_index[l][atomicAdd(&cur, 1)] = 4 * i + 3;
    }
    __syncthreads();
    if (threadIdx.x == 0) g_counts[l] = cur;
}

// ============================================================
// Kernel A: proj partials over K-split.
// projp[ks][b][r] = sum_{k in range} v[l][k][r] * z[b][k]
// grid = (LNUM, MTA, KSPLIT), 64 threads.
// Block tile: 64 samples x 64 r. Thread: 8 samples x 8 r (4 f32x2 r-pairs).
// Zp [k][b] transposed; Vs [k][r] natural (r-pairs consecutive).
// ============================================================
__global__ __launch_bounds__(64) void proj_kernel(const float* __restrict__ z,
                                                  const float* __restrict__ v) {
    const int l = blockIdx.x;
    const int n = g_counts[l];
    const int s0 = blockIdx.y * MTILE;
    if (s0 >= n) return;
    const int k0 = blockIdx.z * KRANGE;

    __shared__ float Zp[KC * ZPS];
    __shared__ float Vs[KC * RDIM];
    __shared__ int   sidx[MTILE];

    const int tid = threadIdx.x;
    {
        int j = s0 + tid;
        sidx[tid] = g_index[l][j < n ? j : n - 1];
    }
    __syncthreads();

    const int ty = tid & 7;     // r octet   -> r 8ty..8ty+7
    const int tx = tid >> 3;    // s octet   -> samples 8tx..8tx+7

    unsigned long long acc[8][4];
#pragma unroll
    for (int s = 0; s < 8; s++)
#pragma unroll
        for (int p = 0; p < 4; p++) acc[s][p] = 0ull;

    const float* vb = v + ((size_t)l * HDIM + k0) * RDIM;
    const int lk = tid & 15;    // z-loader k (coalesced lanes)
    const int lb = tid >> 4;    // z-loader b base (0..3)

    for (int kc = 0; kc < KRANGE; kc += KC) {
        // Z chunk transposed: 16 k x 64 b
#pragma unroll
        for (int i = 0; i < 16; i++) {
            int b = lb + 4 * i;
            Zp[lk * ZPS + b] = z[(size_t)sidx[b] * HDIM + k0 + kc + lk];
        }
        // V chunk: straight copy 16 k x 64 r (natural, coalesced)
        {
            const float4* src = (const float4*)(vb + (size_t)kc * RDIM);
            float4* dst = (float4*)Vs;
#pragma unroll
            for (int i = 0; i < 4; i++) dst[tid + 64 * i] = src[tid + 64 * i];
        }
        __syncthreads();

#pragma unroll
        for (int k = 0; k < KC; k++) {
            float4 zq0 = *(const float4*)(Zp + k * ZPS + 8 * tx);
            float4 zq1 = *(const float4*)(Zp + k * ZPS + 8 * tx + 4);
            unsigned long long zd[8];
            zd[0] = dup2(zq0.x); zd[1] = dup2(zq0.y);
            zd[2] = dup2(zq0.z); zd[3] = dup2(zq0.w);
            zd[4] = dup2(zq1.x); zd[5] = dup2(zq1.y);
            zd[6] = dup2(zq1.z); zd[7] = dup2(zq1.w);
            ulonglong2 va = *(const ulonglong2*)(Vs + k * RDIM + 8 * ty);
            ulonglong2 vc = *(const ulonglong2*)(Vs + k * RDIM + 8 * ty + 4);
#pragma unroll
            for (int s = 0; s < 8; s++) {
                FMA2(acc[s][0], zd[s], va.x);
                FMA2(acc[s][1], zd[s], va.y);
                FMA2(acc[s][2], zd[s], vc.x);
                FMA2(acc[s][3], zd[s], vc.y);
            }
        }
        __syncthreads();
    }

    // store partials: r-pairs are consecutive -> direct float4 stores
    const int ks = blockIdx.z;
#pragma unroll
    for (int s = 0; s < 8; s++) {
        int sl = 8 * tx + s;
        if (s0 + sl < n) {
            float* row = &g_projp[ks][sidx[sl]][8 * ty];
            float4 o0 = make_float4(f2lo(acc[s][0]), f2hi(acc[s][0]),
                                    f2lo(acc[s][1]), f2hi(acc[s][1]));
            float4 o1 = make_float4(f2lo(acc[s][2]), f2hi(acc[s][2]),
                                    f2lo(acc[s][3]), f2hi(acc[s][3]));
            *(float4*)row = o0;
            *(float4*)(row + 4) = o1;
        }
    }
}

// ============================================================
// Kernel A2: reduce K-split partials (fixed order -> deterministic)
// ============================================================
__global__ __launch_bounds__(256) void reduce_kernel() {
    const int idx = blockIdx.x * 256 + threadIdx.x;   // float4 index
    const float4* p = (const float4*)g_projp;
    const int stride = BMAX * RDIM / 4;
    float4 a = p[idx];
#pragma unroll
    for (int s = 1; s < KSPLIT; s++) {
        float4 b = p[s * stride + idx];
        a.x += b.x; a.y += b.y; a.z += b.z; a.w += b.w;
    }
    ((float4*)g_proj)[idx] = a;
}

// ============================================================
// Kernel B: out[b][h] = z[b][h] + sum_r u[l][h][r] * proj[b][r]
// grid = (LNUM, MTA, HDIM/HTILE), 128 threads.
// Block tile: 64 samples x 128 h. Thread: 8 samples x 8 h (4 h-pairs).
// Ps [r][b] transposed; Ut [r][h] transposed (h-pairs consecutive).
// ============================================================
__global__ __launch_bounds__(128) void delta_kernel(const float* __restrict__ z,
                                                    const float* __restrict__ u,
                                                    float* __restrict__ out) {
    const int l = blockIdx.x;
    const int n = g_counts[l];
    const int s0 = blockIdx.y * MTILE;
    if (s0 >= n) return;
    const int hb = blockIdx.z * HTILE;

    __shared__ float Ps[RDIM * PSS];   // [r][b]
    __shared__ float Ut[RC * UTS];     // [r][h] chunk
    __shared__ int   sidx[MTILE];

    const int tid = threadIdx.x;
    if (tid < MTILE) {
        int j = s0 + tid;
        sidx[tid] = g_index[l][j < n ? j : n - 1];
    }
    __syncthreads();

    // Ps fill: transpose proj rows. 2 threads per sample.
    {
        int b = tid >> 1, q = tid & 1;
        const float4* pr = (const float4*)g_proj[sidx[b]];
#pragma unroll
        for (int j = 0; j < 8; j++) {
            float4 pv = pr[q * 8 + j];
            int r0 = q * 32 + 4 * j;
            Ps[(r0 + 0) * PSS + b] = pv.x;
            Ps[(r0 + 1) * PSS + b] = pv.y;
            Ps[(r0 + 2) * PSS + b] = pv.z;
            Ps[(r0 + 3) * PSS + b] = pv.w;
        }
    }

    const int hy = tid & 15;    // h octet  -> h 8hy..8hy+7
    const int tx = tid >> 4;    // s octet  -> samples 8tx..8tx+7

    unsigned long long acc[8][4];
#pragma unroll
    for (int s = 0; s < 8; s++)
#pragma unroll
        for (int p = 0; p < 4; p++) acc[s][p] = 0ull;

    const float* ub = u + ((size_t)l * HDIM + hb) * RDIM;

    for (int rc = 0; rc < RDIM; rc += RC) {
        __syncthreads();   // Ps ready (1st iter) / Ut reuse
        // Ut fill: thread = one h row; transpose 32 r of it
#pragma unroll
        for (int j = 0; j < 8; j++) {
            float4 uu = *(const float4*)(ub + (size_t)tid * RDIM + rc + 4 * j);
            Ut[(4 * j + 0) * UTS + tid] = uu.x;
            Ut[(4 * j + 1) * UTS + tid] = uu.y;
            Ut[(4 * j + 2) * UTS + tid] = uu.z;
            Ut[(4 * j + 3) * UTS + tid] = uu.w;
        }
        __syncthreads();

#pragma unroll 8
        for (int r = 0; r < RC; r++) {
            float4 pq0 = *(const float4*)(Ps + (rc + r) * PSS + 8 * tx);
            float4 pq1 = *(const float4*)(Ps + (rc + r) * PSS + 8 * tx + 4);
            unsigned long long pd[8];
            pd[0] = dup2(pq0.x); pd[1] = dup2(pq0.y);
            pd[2] = dup2(pq0.z); pd[3] = dup2(pq0.w);
            pd[4] = dup2(pq1.x); pd[5] = dup2(pq1.y);
            pd[6] = dup2(pq1.z); pd[7] = dup2(pq1.w);
            ulonglong2 ua = *(const ulonglong2*)(Ut + r * UTS + 8 * hy);
            ulonglong2 uc = *(const ulonglong2*)(Ut + r * UTS + 8 * hy + 4);
#pragma unroll
            for (int s = 0; s < 8; s++) {
                FMA2(acc[s][0], pd[s], ua.x);
                FMA2(acc[s][1], pd[s], ua.y);
                FMA2(acc[s][2], pd[s], uc.x);
                FMA2(acc[s][3], pd[s], uc.y);
            }
        }
    }

    // epilogue: h-pairs consecutive -> two float4 per sample
#pragma unroll
    for (int s = 0; s < 8; s++) {
        int sl = 8 * tx + s;
        if (s0 + sl < n) {
            size_t off = (size_t)sidx[sl] * HDIM + hb + 8 * hy;
            float4 zz0 = *(const float4*)(z + off);
            float4 zz1 = *(const float4*)(z + off + 4);
            float4 o0 = make_float4(zz0.x + f2lo(acc[s][0]), zz0.y + f2hi(acc[s][0]),
                                    zz0.z + f2lo(acc[s][1]), zz0.w + f2hi(acc[s][1]));
            float4 o1 = make_float4(zz1.x + f2lo(acc[s][2]), zz1.y + f2hi(acc[s][2]),
                                    zz1.z + f2lo(acc[s][3]), zz1.w + f2hi(acc[s][3]));
            *(float4*)(out + off) = o0;
            *(float4*)(out + off + 4) = o1;
        }
    }
}

// ============================================================
extern "C" void kernel_launch(void* const* d_in, const int* in_sizes, int n_in,
                              void* d_out, int out_size) {
    const float* z   = (const float*)d_in[0];
    const int*   lid = (const int*)d_in[1];
    const float* u   = (const float*)d_in[2];
    const float* v   = (const float*)d_in[3];
    float* out = (float*)d_out;
    const int B = in_sizes[1];

    bucket_kernel<<<LNUM, 256>>>(lid, B);
    proj_kernel<<<dim3(LNUM, MTA, KSPLIT), 64>>>(z, v);
    reduce_kernel<<<(BMAX * RDIM / 4) / 256, 256>>>();
    delta_kernel<<<dim3(LNUM, MTA, HDIM / HTILE), 128>>>(z, u, out);
}

// round 11
// speedup vs baseline: 2.7532x; 1.9045x over previous
#include <cuda_runtime.h>
#include <cuda_bf16.h>
#include <cstdint>

// LayerwiseLowRankUplift: out = z + U_l (V_l^T z), per-sample layer l.
// B=2048, H=2048, R=64, L=32.
// R10: warp-level mma.sync bf16 (HMMA) for both GEMMs; tcgen05 PTX is
// rejected by this toolchain's sm_103 ptxas target. fp32 accum + fp32 z add.

#define HDIM 2048
#define RDIM 64
#define LNUM 32
#define BMAX 2048

#define KSPLIT 16
#define KRANGE (HDIM / KSPLIT)   // 128
#define KC     64                // K chunk in smem per fill

#define RS 72                    // smem row stride in bf16 (144 B)
#define RSW 36                   // row stride in uint32 words

// ---- scratch ----
__device__ int   g_counts[LNUM];
__device__ int   g_index[LNUM][BMAX];
__device__ float g_projp[KSPLIT][BMAX][RDIM];   // 8 MB partials
__device__ float g_proj[BMAX][RDIM];

__device__ __forceinline__ uint32_t pack_bf2(float lo, float hi) {
    uint32_t r;
    asm("cvt.rn.bf16x2.f32 %0, %1, %2;" : "=r"(r) : "f"(hi), "f"(lo));
    return r;
}

// D = A*B + D : m16n8k16, bf16 in, fp32 accum
#define MMA16816(c, a0, a1, a2, a3, b0, b1) \
    asm volatile("mma.sync.aligned.m16n8k16.row.col.f32.bf16.bf16.f32 " \
        "{%0,%1,%2,%3}, {%4,%5,%6,%7}, {%8,%9}, {%0,%1,%2,%3};" \
        : "+f"((c)[0]), "+f"((c)[1]), "+f"((c)[2]), "+f"((c)[3]) \
        : "r"(a0), "r"(a1), "r"(a2), "r"(a3), "r"(b0), "r"(b1))

// ============================================================
// Kernel 0: bucket sample indices by layer (warp-aggregated atomics).
// ============================================================
__global__ __launch_bounds__(256) void bucket_kernel(const int* __restrict__ ids, int B) {
    __shared__ int cur;
    const int l = blockIdx.x;
    const int lane = threadIdx.x & 31;
    if (threadIdx.x == 0) cur = 0;
    __syncthreads();
    for (int i = threadIdx.x; i < B; i += 256) {
        bool m = (ids[i] == l);
        unsigned bal = __ballot_sync(0xffffffffu, m);
        if (bal) {
            int leader = __ffs(bal) - 1;
            int base = 0;
            if (lane == leader) base = atomicAdd(&cur, __popc(bal));
            base = __shfl_sync(0xffffffffu, base, leader);
            if (m) g_index[l][base + __popc(bal & ((1u << lane) - 1u))] = i;
        }
    }
    __syncthreads();
    if (threadIdx.x == 0) g_counts[l] = cur;
}

// ============================================================
// Kernel A: proj partials. projp[ks][b][r] = sum_{k in split} z[b][k]*v[l][k][r]
// grid (LNUM, 2, KSPLIT), 256 threads (8 warps).
// A = Z gathered [128 s][KC k] bf16; B = V^T [64 r][KC k] bf16.
// Warp w: M-stripe rows 16w..16w+15, all 64 N cols.
// ============================================================
__global__ __launch_bounds__(256) void proj_mma(const float* __restrict__ z,
                                                const float* __restrict__ v) {
    const int l = blockIdx.x;
    const int n = g_counts[l];
    const int s0 = blockIdx.y * 128;
    if (s0 >= n) return;
    const int k0 = blockIdx.z * KRANGE;

    __shared__ __align__(16) __nv_bfloat16 Zt[128 * RS];
    __shared__ __align__(16) __nv_bfloat16 Vt[64 * RS];
    __shared__ int sidx[128];

    const int tid = threadIdx.x, wid = tid >> 5, lane = tid & 31;
    const int qr = lane >> 2, qc = lane & 3;
    {
        int j = s0 + (tid & 127);
        sidx[tid & 127] = g_index[l][j < n ? j : n - 1];
    }
    __syncthreads();

    float acc[8][4];
#pragma unroll
    for (int t = 0; t < 8; t++)
#pragma unroll
        for (int j = 0; j < 4; j++) acc[t][j] = 0.f;

    const float* vbase = v + (size_t)l * HDIM * RDIM;
    const uint32_t* Z32 = (const uint32_t*)Zt;
    const uint32_t* V32 = (const uint32_t*)Vt;
    const int m0 = wid * 16;

    for (int kc = 0; kc < KRANGE; kc += KC) {
        __syncthreads();   // smem reuse
        // --- fill Z: row = tid>>1, half = tid&1 covers 32 k ---
        {
            const int row = tid >> 1, half = tid & 1;
            const float4* src = (const float4*)(z + (size_t)sidx[row] * HDIM
                                                + k0 + kc + half * 32);
            uint2* dst = (uint2*)(Zt + row * RS + half * 32);
#pragma unroll
            for (int j = 0; j < 8; j++) {
                float4 x = src[j];
                dst[j] = make_uint2(pack_bf2(x.x, x.y), pack_bf2(x.z, x.w));
            }
        }
        // --- fill V^T: r = tid&63, kq = tid>>6 covers 16 k ---
        {
            const int r = tid & 63, kq = tid >> 6;
            uint32_t* dst = (uint32_t*)(Vt + r * RS + kq * 16);
#pragma unroll
            for (int j = 0; j < 8; j++) {
                int k = kc + kq * 16 + 2 * j;
                float f0 = vbase[(size_t)(k0 + k) * RDIM + r];
                float f1 = vbase[(size_t)(k0 + k + 1) * RDIM + r];
                dst[j] = pack_bf2(f0, f1);
            }
        }
        __syncthreads();

#pragma unroll
        for (int kt = 0; kt < KC / 16; kt++) {
            uint32_t a0 = Z32[(m0 + qr) * RSW + kt * 8 + qc];
            uint32_t a1 = Z32[(m0 + qr + 8) * RSW + kt * 8 + qc];
            uint32_t a2 = Z32[(m0 + qr) * RSW + kt * 8 + 4 + qc];
            uint32_t a3 = Z32[(m0 + qr + 8) * RSW + kt * 8 + 4 + qc];
#pragma unroll
            for (int nt = 0; nt < 8; nt++) {
                uint32_t b0 = V32[(nt * 8 + qr) * RSW + kt * 8 + qc];
                uint32_t b1 = V32[(nt * 8 + qr) * RSW + kt * 8 + 4 + qc];
                MMA16816(acc[nt], a0, a1, a2, a3, b0, b1);
            }
        }
    }

    // epilogue: c0,c1 -> (m0+qr, nt*8+2qc), c2,c3 -> row +8
    const int ks = blockIdx.z;
    const int r1 = m0 + qr, r2 = r1 + 8;
    const bool v1 = (s0 + r1 < n), v2 = (s0 + r2 < n);
    float* p1 = g_projp[ks][sidx[r1]];
    float* p2 = g_projp[ks][sidx[r2]];
#pragma unroll
    for (int nt = 0; nt < 8; nt++) {
        int c = nt * 8 + 2 * qc;
        if (v1) *(float2*)(p1 + c) = make_float2(acc[nt][0], acc[nt][1]);
        if (v2) *(float2*)(p2 + c) = make_float2(acc[nt][2], acc[nt][3]);
    }
}

// ============================================================
// Kernel A2: reduce K-split partials (fixed order -> deterministic)
// ============================================================
__global__ __launch_bounds__(256) void reduce_kernel() {
    const int idx = blockIdx.x * 256 + threadIdx.x;   // float4 index
    const float4* p = (const float4*)g_projp;
    const int stride = BMAX * RDIM / 4;
    float4 a = p[idx];
#pragma unroll
    for (int s = 1; s < KSPLIT; s++) {
        float4 b = p[s * stride + idx];
        a.x += b.x; a.y += b.y; a.z += b.z; a.w += b.w;
    }
    ((float4*)g_proj)[idx] = a;
}

// ============================================================
// Kernel B: out[b][h] = z[b][h] + sum_r proj[b][r] * u[l][h][r]
// grid (LNUM, 2, HDIM/128), 256 threads (8 warps).
// A = proj gathered [128 s][64 r]; B = U tile [128 h][64 r] (natural K-major).
// Warp w: M-stripe 16 rows x 128 h. A frags hoisted; loop 16 n-tiles.
// ============================================================
__global__ __launch_bounds__(256) void delta_mma(const float* __restrict__ z,
                                                 const float* __restrict__ u,
                                                 float* __restrict__ out) {
    const int l = blockIdx.x;
    const int n = g_counts[l];
    const int s0 = blockIdx.y * 128;
    if (s0 >= n) return;
    const int hb = blockIdx.z * 128;

    __shared__ __align__(16) __nv_bfloat16 Pt[128 * RS];
    __shared__ __align__(16) __nv_bfloat16 Ut[128 * RS];
    __shared__ int sidx[128];

    const int tid = threadIdx.x, wid = tid >> 5, lane = tid & 31;
    const int qr = lane >> 2, qc = lane & 3;
    {
        int j = s0 + (tid & 127);
        sidx[tid & 127] = g_index[l][j < n ? j : n - 1];
    }
    __syncthreads();

    // --- fill P (gathered proj rows) and U (natural rows), 64 floats each ---
    {
        const int row = tid >> 1, half = tid & 1;
        {
            const float4* src = (const float4*)(g_proj[sidx[row]] + half * 32);
            uint2* dst = (uint2*)(Pt + row * RS + half * 32);
#pragma unroll
            for (int j = 0; j < 8; j++) {
                float4 x = src[j];
                dst[j] = make_uint2(pack_bf2(x.x, x.y), pack_bf2(x.z, x.w));
            }
        }
        {
            const float4* src = (const float4*)(u + ((size_t)l * HDIM + hb + row) * RDIM
                                                + half * 32);
            uint2* dst = (uint2*)(Ut + row * RS + half * 32);
#pragma unroll
            for (int j = 0; j < 8; j++) {
                float4 x = src[j];
                dst[j] = make_uint2(pack_bf2(x.x, x.y), pack_bf2(x.z, x.w));
            }
        }
    }
    __syncthreads();

    const uint32_t* P32 = (const uint32_t*)Pt;
    const uint32_t* U32 = (const uint32_t*)Ut;
    const int m0 = wid * 16;

    // hoist A fragments for all 4 k-tiles (K=64)
    uint32_t a[4][4];
#pragma unroll
    for (int kt = 0; kt < 4; kt++) {
        a[kt][0] = P32[(m0 + qr) * RSW + kt * 8 + qc];
        a[kt][1] = P32[(m0 + qr + 8) * RSW + kt * 8 + qc];
        a[kt][2] = P32[(m0 + qr) * RSW + kt * 8 + 4 + qc];
        a[kt][3] = P32[(m0 + qr + 8) * RSW + kt * 8 + 4 + qc];
    }

    const int r1 = m0 + qr, r2 = r1 + 8;
    const bool v1 = (s0 + r1 < n), v2 = (s0 + r2 < n);
    const size_t o1 = (size_t)sidx[r1] * HDIM + hb;
    const size_t o2 = (size_t)sidx[r2] * HDIM + hb;

#pragma unroll
    for (int nt = 0; nt < 16; nt++) {
        float acc[4] = {0.f, 0.f, 0.f, 0.f};
#pragma unroll
        for (int kt = 0; kt < 4; kt++) {
            uint32_t b0 = U32[(nt * 8 + qr) * RSW + kt * 8 + qc];
            uint32_t b1 = U32[(nt * 8 + qr) * RSW + kt * 8 + 4 + qc];
            MMA16816(acc, a[kt][0], a[kt][1], a[kt][2], a[kt][3], b0, b1);
        }
        const int c = nt * 8 + 2 * qc;
        if (v1) {
            float2 zz = *(const float2*)(z + o1 + c);
            *(float2*)(out + o1 + c) = make_float2(zz.x + acc[0], zz.y + acc[1]);
        }
        if (v2) {
            float2 zz = *(const float2*)(z + o2 + c);
            *(float2*)(out + o2 + c) = make_float2(zz.x + acc[2], zz.y + acc[3]);
        }
    }
}

// ============================================================
extern "C" void kernel_launch(void* const* d_in, const int* in_sizes, int n_in,
                              void* d_out, int out_size) {
    const float* z   = (const float*)d_in[0];
    const int*   lid = (const int*)d_in[1];
    const float* u   = (const float*)d_in[2];
    const float* v   = (const float*)d_in[3];
    float* out = (float*)d_out;
    const int B = in_sizes[1];

    bucket_kernel<<<LNUM, 256>>>(lid, B);
    proj_mma<<<dim3(LNUM, 2, KSPLIT), 256>>>(z, v);
    reduce_kernel<<<(BMAX * RDIM / 4) / 256, 256>>>();
    delta_mma<<<dim3(LNUM, 2, HDIM / 128), 256>>>(z, u, out);
}